// round 1
// baseline (speedup 1.0000x reference)
#include <cuda_runtime.h>
#include <math.h>

// Problem constants (fixed by the reference)
#define BATCH 8
#define TT    4096
#define DD    768
#define HH    768
#define MM    (BATCH * TT)      // 32768 flattened rows
#define CHUNK 128
#define NC    (TT / CHUNK)      // 32 chunks

// Scratch (static device globals: allocation-free per harness rules)
__device__ float g_A [(size_t)MM * HH];   // a_t  = f'_t            (100.7 MB)
__device__ float g_Bv[(size_t)MM * HH];   // b_t  = i'_t * h~_t     (100.7 MB)
__device__ float g_aggA[BATCH * NC * HH]; // per-chunk prod(a)
__device__ float g_aggB[BATCH * NC * HH]; // per-chunk combined b
__device__ float g_pref[BATCH * NC * HH]; // h before each chunk

// ---------------------------------------------------------------------------
// Kernel 1: fused triple GEMM + gate epilogue.
//   f = sigmoid(x @ fw^T + fb); i = sigmoid(x @ iw^T + ib); ht = x @ hw^T + hb
//   den = f + i + 1e-8;  a = f/den;  b = (i/den)*ht
// Tile: BM=64 (rows of x), BN=64 (hidden units), BK=16. 256 threads,
// each thread computes a 4x4 microtile for all 3 projections.
// ---------------------------------------------------------------------------
#define BM 64
#define BN 64
#define BK 16

__global__ __launch_bounds__(256, 2)
void gates_gemm_kernel(const float* __restrict__ x,
                       const float* __restrict__ fw, const float* __restrict__ fb,
                       const float* __restrict__ iw, const float* __restrict__ ib,
                       const float* __restrict__ hw, const float* __restrict__ hb)
{
    __shared__ float xs [BK][BM];
    __shared__ float wfs[BK][BN];
    __shared__ float wis[BK][BN];
    __shared__ float whs[BK][BN];

    const int tid = threadIdx.x;
    const int tx  = tid & 15;          // n direction (4 cols each)
    const int ty  = tid >> 4;          // m direction (4 rows each)
    const int n0  = blockIdx.x * BN;
    const int m0  = blockIdx.y * BM;

    const int lk = tid & 15;           // k lane for loads
    const int lr = tid >> 4;           // row group for loads

    float cf[4][4] = {}, ci[4][4] = {}, ch[4][4] = {};

    for (int k0 = 0; k0 < DD; k0 += BK) {
        // Load x tile (64 rows x 16 k)
        #pragma unroll
        for (int r = 0; r < 4; r++) {
            int mm = lr + r * 16;
            xs[lk][mm] = x[(size_t)(m0 + mm) * DD + k0 + lk];
        }
        // Load 3 weight tiles (64 cols x 16 k), weights are (H, D) row-major
        #pragma unroll
        for (int r = 0; r < 4; r++) {
            int nn = lr + r * 16;
            size_t wi_ = (size_t)(n0 + nn) * DD + k0 + lk;
            wfs[lk][nn] = fw[wi_];
            wis[lk][nn] = iw[wi_];
            whs[lk][nn] = hw[wi_];
        }
        __syncthreads();

        #pragma unroll
        for (int k = 0; k < BK; k++) {
            float4 rx4 = *(const float4*)&xs [k][ty * 4];
            float4 f4  = *(const float4*)&wfs[k][tx * 4];
            float4 i4  = *(const float4*)&wis[k][tx * 4];
            float4 h4  = *(const float4*)&whs[k][tx * 4];
            float ra[4] = {rx4.x, rx4.y, rx4.z, rx4.w};
            float bf[4] = {f4.x,  f4.y,  f4.z,  f4.w };
            float bi[4] = {i4.x,  i4.y,  i4.z,  i4.w };
            float bh[4] = {h4.x,  h4.y,  h4.z,  h4.w };
            #pragma unroll
            for (int a = 0; a < 4; a++) {
                #pragma unroll
                for (int b = 0; b < 4; b++) {
                    cf[a][b] = fmaf(ra[a], bf[b], cf[a][b]);
                    ci[a][b] = fmaf(ra[a], bi[b], ci[a][b]);
                    ch[a][b] = fmaf(ra[a], bh[b], ch[a][b]);
                }
            }
        }
        __syncthreads();
    }

    // Epilogue: gates -> (a, b) scan coefficients
    #pragma unroll
    for (int a = 0; a < 4; a++) {
        int m = m0 + ty * 4 + a;
        #pragma unroll
        for (int b = 0; b < 4; b++) {
            int h = n0 + tx * 4 + b;
            float fv = 1.0f / (1.0f + __expf(-(cf[a][b] + fb[h])));
            float iv = 1.0f / (1.0f + __expf(-(ci[a][b] + ib[h])));
            float ht = ch[a][b] + hb[h];
            float inv_den = 1.0f / (fv + iv + 1e-8f);
            size_t o = (size_t)m * HH + h;
            g_A [o] = fv * inv_den;
            g_Bv[o] = iv * inv_den * ht;
        }
    }
}

// ---------------------------------------------------------------------------
// Kernel 2 (phase A): per-chunk affine aggregate.
//   For chunk c of lane (b,h): Ap = prod a_t ; Bc = fold(a,b) over chunk.
// idx layout: h fastest (coalesced), then chunk, then batch.
// ---------------------------------------------------------------------------
__global__ void scan_phaseA_kernel()
{
    int idx = blockIdx.x * blockDim.x + threadIdx.x;  // < BATCH*NC*HH
    int h   = idx % HH;
    int rem = idx / HH;
    int c   = rem % NC;
    int b   = rem / NC;

    size_t base = ((size_t)b * TT + (size_t)c * CHUNK) * HH + h;
    float Ap = 1.0f, Bc = 0.0f;
    #pragma unroll 4
    for (int t = 0; t < CHUNK; t++) {
        float a  = g_A [base + (size_t)t * HH];
        float bb = g_Bv[base + (size_t)t * HH];
        Bc = fmaf(a, Bc, bb);   // combine: b <- a_new*b_prev + b_new
        Ap = Ap * a;
    }
    g_aggA[idx] = Ap;
    g_aggB[idx] = Bc;
}

// ---------------------------------------------------------------------------
// Kernel 3 (phase B): serial composition of the NC=32 chunk aggregates per
// (b,h) lane; records the h value entering each chunk. 6144 threads, tiny.
// ---------------------------------------------------------------------------
__global__ void scan_phaseB_kernel(const float* __restrict__ h0)
{
    int idx = blockIdx.x * blockDim.x + threadIdx.x;  // < BATCH*HH
    int h = idx % HH;
    int b = idx / HH;

    float hp = h0[(size_t)b * HH + h];
    #pragma unroll
    for (int c = 0; c < NC; c++) {
        size_t ai = ((size_t)b * NC + c) * HH + h;
        g_pref[ai] = hp;
        hp = fmaf(g_aggA[ai], hp, g_aggB[ai]);
    }
}

// ---------------------------------------------------------------------------
// Kernel 4 (phase C): replay each chunk with its prefix, write h_t to out.
// ---------------------------------------------------------------------------
__global__ void scan_phaseC_kernel(float* __restrict__ out)
{
    int idx = blockIdx.x * blockDim.x + threadIdx.x;  // < BATCH*NC*HH
    int h   = idx % HH;
    int rem = idx / HH;
    int c   = rem % NC;
    int b   = rem / NC;

    size_t base = ((size_t)b * TT + (size_t)c * CHUNK) * HH + h;
    float hcur = g_pref[idx];
    #pragma unroll 4
    for (int t = 0; t < CHUNK; t++) {
        size_t o = base + (size_t)t * HH;
        hcur = fmaf(g_A[o], hcur, g_Bv[o]);
        out[o] = hcur;
    }
}

// ---------------------------------------------------------------------------
extern "C" void kernel_launch(void* const* d_in, const int* in_sizes, int n_in,
                              void* d_out, int out_size)
{
    const float* x  = (const float*)d_in[0];
    const float* h0 = (const float*)d_in[1];
    const float* fw = (const float*)d_in[2];
    const float* fb = (const float*)d_in[3];
    const float* iw = (const float*)d_in[4];
    const float* ib = (const float*)d_in[5];
    const float* hw = (const float*)d_in[6];
    const float* hb = (const float*)d_in[7];
    float* out = (float*)d_out;

    // 1) gates GEMM: grid (N tiles, M tiles)
    dim3 ggrid(HH / BN, MM / BM);     // (12, 512)
    gates_gemm_kernel<<<ggrid, 256>>>(x, fw, fb, iw, ib, hw, hb);

    // 2) chunk aggregates: BATCH*NC*HH = 196608 threads
    scan_phaseA_kernel<<<(BATCH * NC * HH) / 256, 256>>>();

    // 3) chunk prefix composition: BATCH*HH = 6144 threads
    scan_phaseB_kernel<<<(BATCH * HH) / 256, 256>>>(h0);

    // 4) replay + write output
    scan_phaseC_kernel<<<(BATCH * NC * HH) / 256, 256>>>(out);
}

// round 4
// speedup vs baseline: 4.5944x; 4.5944x over previous
#include <cuda_runtime.h>
#include <math.h>
#include <stdint.h>

// Problem constants (fixed by the reference)
#define BATCH 8
#define TT    4096
#define DD    768
#define HH    768
#define MM    (BATCH * TT)      // 32768 flattened rows
#define CHUNK 128
#define NC    (TT / CHUNK)      // 32 chunks

// Scratch (static device globals: allocation-free per harness rules)
__device__ float g_A [(size_t)MM * HH];   // a_t  = f'_t            (100.7 MB)
__device__ float g_Bv[(size_t)MM * HH];   // b_t  = i'_t * h~_t     (100.7 MB)
__device__ float g_aggA[BATCH * NC * HH]; // per-chunk prod(a)
__device__ float g_aggB[BATCH * NC * HH]; // per-chunk combined b
__device__ float g_pref[BATCH * NC * HH]; // h before each chunk

// ---------------------------------------------------------------------------
// Kernel 1: fused triple GEMM (tf32 tensor cores) + gate epilogue.
// Tile: BM=64 x BN=64 x BK=32. 8 warps (2 m x 4 n), each warp 32x16 via
// 2x2 m16n8k8 tf32 mma tiles, 3 projections simultaneously.
// ---------------------------------------------------------------------------
#define BM 64
#define BN 64
#define BK 32
#define BKP 36   // padded stride: bank = (4r + c) % 32 -> conflict-free frags

// cvt to tf32: destination MUST be .b32 (that was the R1 ptxas failure)
__device__ __forceinline__ float tf32r(float f) {
    uint32_t u;
    asm("cvt.rna.tf32.f32 %0, %1;" : "=r"(u) : "f"(f));
    return __uint_as_float(u);
}

__device__ __forceinline__ void mma_tf32(float& c0, float& c1, float& c2, float& c3,
                                         uint32_t a0, uint32_t a1, uint32_t a2, uint32_t a3,
                                         uint32_t b0, uint32_t b1) {
    asm volatile(
        "mma.sync.aligned.m16n8k8.row.col.f32.tf32.tf32.f32 "
        "{%0,%1,%2,%3}, {%4,%5,%6,%7}, {%8,%9}, {%0,%1,%2,%3};\n"
        : "+f"(c0), "+f"(c1), "+f"(c2), "+f"(c3)
        : "r"(a0), "r"(a1), "r"(a2), "r"(a3), "r"(b0), "r"(b1));
}

__global__ __launch_bounds__(256, 2)
void gates_gemm_kernel(const float* __restrict__ x,
                       const float* __restrict__ fw, const float* __restrict__ fb,
                       const float* __restrict__ iw, const float* __restrict__ ib,
                       const float* __restrict__ hw, const float* __restrict__ hb)
{
    __shared__ float xs [BM * BKP];
    __shared__ float ws0[BN * BKP];
    __shared__ float ws1[BN * BKP];
    __shared__ float ws2[BN * BKP];

    const int tid = threadIdx.x;
    const int L   = tid & 31;
    const int w   = tid >> 5;
    const int wm  = w >> 2;          // 0..1 -> 32 rows
    const int wn  = w & 3;           // 0..3 -> 16 cols
    const int m0b = blockIdx.y * BM;
    const int n0b = blockIdx.x * BN;

    // load mapping: 512 float4 per tile, 2 per thread
    const int er0 = tid >> 3;              // row for j=0 (0..31)
    const int ec0 = (tid & 7) * 4;         // col
    const int er1 = er0 + 32;              // row for j=1

    // fragment base indices
    const int fr = L >> 2;                 // 0..7
    const int fc = L & 3;                  // 0..3

    float cf[2][2][4] = {}, ci[2][2][4] = {}, ch[2][2][4] = {};
    float4 rx[2], rwf[2], rwi[2], rwh[2];

    // ---- helpers (macros to keep regs tight) ----
#define LOAD_REGS(K0)                                                          \
    {                                                                          \
        rx [0] = *(const float4*)&x [(size_t)(m0b + er0) * DD + (K0) + ec0];   \
        rx [1] = *(const float4*)&x [(size_t)(m0b + er1) * DD + (K0) + ec0];   \
        rwf[0] = *(const float4*)&fw[(size_t)(n0b + er0) * DD + (K0) + ec0];   \
        rwf[1] = *(const float4*)&fw[(size_t)(n0b + er1) * DD + (K0) + ec0];   \
        rwi[0] = *(const float4*)&iw[(size_t)(n0b + er0) * DD + (K0) + ec0];   \
        rwi[1] = *(const float4*)&iw[(size_t)(n0b + er1) * DD + (K0) + ec0];   \
        rwh[0] = *(const float4*)&hw[(size_t)(n0b + er0) * DD + (K0) + ec0];   \
        rwh[1] = *(const float4*)&hw[(size_t)(n0b + er1) * DD + (K0) + ec0];   \
    }

#define CVT4(V) { (V).x = tf32r((V).x); (V).y = tf32r((V).y); (V).z = tf32r((V).z); (V).w = tf32r((V).w); }

#define STORE_SMEM()                                                           \
    {                                                                          \
        CVT4(rx[0]);  CVT4(rx[1]);  CVT4(rwf[0]); CVT4(rwf[1]);                \
        CVT4(rwi[0]); CVT4(rwi[1]); CVT4(rwh[0]); CVT4(rwh[1]);                \
        *(float4*)&xs [er0 * BKP + ec0] = rx [0];                              \
        *(float4*)&xs [er1 * BKP + ec0] = rx [1];                              \
        *(float4*)&ws0[er0 * BKP + ec0] = rwf[0];                              \
        *(float4*)&ws0[er1 * BKP + ec0] = rwf[1];                              \
        *(float4*)&ws1[er0 * BKP + ec0] = rwi[0];                              \
        *(float4*)&ws1[er1 * BKP + ec0] = rwi[1];                              \
        *(float4*)&ws2[er0 * BKP + ec0] = rwh[0];                              \
        *(float4*)&ws2[er1 * BKP + ec0] = rwh[1];                              \
    }

#define COMPUTE()                                                              \
    {                                                                          \
        _Pragma("unroll")                                                      \
        for (int kk = 0; kk < BK; kk += 8) {                                   \
            uint32_t A[2][4];                                                  \
            _Pragma("unroll")                                                  \
            for (int mt = 0; mt < 2; mt++) {                                   \
                int mr = wm * 32 + mt * 16 + fr;                               \
                A[mt][0] = __float_as_uint(xs[(mr    ) * BKP + kk + fc    ]);  \
                A[mt][1] = __float_as_uint(xs[(mr + 8) * BKP + kk + fc    ]);  \
                A[mt][2] = __float_as_uint(xs[(mr    ) * BKP + kk + fc + 4]);  \
                A[mt][3] = __float_as_uint(xs[(mr + 8) * BKP + kk + fc + 4]);  \
            }                                                                  \
            _Pragma("unroll")                                                  \
            for (int nt = 0; nt < 2; nt++) {                                   \
                int nb = (wn * 16 + nt * 8 + (L >> 2)) * BKP + kk + (L & 3);   \
                uint32_t bf0 = __float_as_uint(ws0[nb]);                       \
                uint32_t bf1 = __float_as_uint(ws0[nb + 4]);                   \
                uint32_t bi0 = __float_as_uint(ws1[nb]);                       \
                uint32_t bi1 = __float_as_uint(ws1[nb + 4]);                   \
                uint32_t bh0 = __float_as_uint(ws2[nb]);                       \
                uint32_t bh1 = __float_as_uint(ws2[nb + 4]);                   \
                _Pragma("unroll")                                              \
                for (int mt = 0; mt < 2; mt++) {                               \
                    mma_tf32(cf[mt][nt][0], cf[mt][nt][1], cf[mt][nt][2], cf[mt][nt][3], \
                             A[mt][0], A[mt][1], A[mt][2], A[mt][3], bf0, bf1);\
                    mma_tf32(ci[mt][nt][0], ci[mt][nt][1], ci[mt][nt][2], ci[mt][nt][3], \
                             A[mt][0], A[mt][1], A[mt][2], A[mt][3], bi0, bi1);\
                    mma_tf32(ch[mt][nt][0], ch[mt][nt][1], ch[mt][nt][2], ch[mt][nt][3], \
                             A[mt][0], A[mt][1], A[mt][2], A[mt][3], bh0, bh1);\
                }                                                              \
            }                                                                  \
        }                                                                      \
    }

    // ---- pipeline: prefetch-to-regs double buffering ----
    LOAD_REGS(0);
    STORE_SMEM();
    __syncthreads();
    for (int k0 = BK; k0 < DD; k0 += BK) {
        LOAD_REGS(k0);
        COMPUTE();
        __syncthreads();
        STORE_SMEM();
        __syncthreads();
    }
    COMPUTE();

    // ---- epilogue: gates -> (a, b) scan coefficients ----
    #pragma unroll
    for (int mt = 0; mt < 2; mt++) {
        #pragma unroll
        for (int nt = 0; nt < 2; nt++) {
            int rbase = m0b + wm * 32 + mt * 16 + (L >> 2);
            int cbase = n0b + wn * 16 + nt * 8 + 2 * (L & 3);
            #pragma unroll
            for (int e = 0; e < 4; e++) {
                int m = rbase + ((e >> 1) ? 8 : 0);
                int h = cbase + (e & 1);
                float fv = 1.0f / (1.0f + __expf(-(cf[mt][nt][e] + fb[h])));
                float iv = 1.0f / (1.0f + __expf(-(ci[mt][nt][e] + ib[h])));
                float ht = ch[mt][nt][e] + hb[h];
                float inv_den = 1.0f / (fv + iv + 1e-8f);
                size_t o = (size_t)m * HH + h;
                g_A [o] = fv * inv_den;
                g_Bv[o] = iv * inv_den * ht;
            }
        }
    }
#undef LOAD_REGS
#undef CVT4
#undef STORE_SMEM
#undef COMPUTE
}

// ---------------------------------------------------------------------------
// Kernel 2 (phase A): per-chunk affine aggregate.
// ---------------------------------------------------------------------------
__global__ void scan_phaseA_kernel()
{
    int idx = blockIdx.x * blockDim.x + threadIdx.x;  // < BATCH*NC*HH
    int h   = idx % HH;
    int rem = idx / HH;
    int c   = rem % NC;
    int b   = rem / NC;

    size_t base = ((size_t)b * TT + (size_t)c * CHUNK) * HH + h;
    float Ap = 1.0f, Bc = 0.0f;
    #pragma unroll 4
    for (int t = 0; t < CHUNK; t++) {
        float a  = g_A [base + (size_t)t * HH];
        float bb = g_Bv[base + (size_t)t * HH];
        Bc = fmaf(a, Bc, bb);
        Ap = Ap * a;
    }
    g_aggA[idx] = Ap;
    g_aggB[idx] = Bc;
}

// ---------------------------------------------------------------------------
// Kernel 3 (phase B): serial composition across chunks. Tiny.
// ---------------------------------------------------------------------------
__global__ void scan_phaseB_kernel(const float* __restrict__ h0)
{
    int idx = blockIdx.x * blockDim.x + threadIdx.x;  // < BATCH*HH
    int h = idx % HH;
    int b = idx / HH;

    float hp = h0[(size_t)b * HH + h];
    #pragma unroll
    for (int c = 0; c < NC; c++) {
        size_t ai = ((size_t)b * NC + c) * HH + h;
        g_pref[ai] = hp;
        hp = fmaf(g_aggA[ai], hp, g_aggB[ai]);
    }
}

// ---------------------------------------------------------------------------
// Kernel 4 (phase C): replay each chunk with its prefix, write h_t to out.
// ---------------------------------------------------------------------------
__global__ void scan_phaseC_kernel(float* __restrict__ out)
{
    int idx = blockIdx.x * blockDim.x + threadIdx.x;  // < BATCH*NC*HH
    int h   = idx % HH;
    int rem = idx / HH;
    int c   = rem % NC;
    int b   = rem / NC;

    size_t base = ((size_t)b * TT + (size_t)c * CHUNK) * HH + h;
    float hcur = g_pref[idx];
    #pragma unroll 4
    for (int t = 0; t < CHUNK; t++) {
        size_t o = base + (size_t)t * HH;
        hcur = fmaf(g_A[o], hcur, g_Bv[o]);
        out[o] = hcur;
    }
}

// ---------------------------------------------------------------------------
extern "C" void kernel_launch(void* const* d_in, const int* in_sizes, int n_in,
                              void* d_out, int out_size)
{
    const float* x  = (const float*)d_in[0];
    const float* h0 = (const float*)d_in[1];
    const float* fw = (const float*)d_in[2];
    const float* fb = (const float*)d_in[3];
    const float* iw = (const float*)d_in[4];
    const float* ib = (const float*)d_in[5];
    const float* hw = (const float*)d_in[6];
    const float* hb = (const float*)d_in[7];
    float* out = (float*)d_out;

    dim3 ggrid(HH / BN, MM / BM);     // (12, 512)
    gates_gemm_kernel<<<ggrid, 256>>>(x, fw, fb, iw, ib, hw, hb);

    scan_phaseA_kernel<<<(BATCH * NC * HH) / 256, 256>>>();
    scan_phaseB_kernel<<<(BATCH * HH) / 256, 256>>>(h0);
    scan_phaseC_kernel<<<(BATCH * NC * HH) / 256, 256>>>(out);
}